// round 10
// baseline (speedup 1.0000x reference)
#include <cuda_runtime.h>
#include <cuda_bf16.h>
#include <cstdint>

// CTC forward negative log-likelihood (keras ctc_batch_cost semantics).
// B=128, T=1024, V=512, L=128, S=2L+1=257, blank=V-1.
//
// Round-10 design ("parity-specialized ghost zone, 2 steps per barrier"):
//  - 1 CTA per batch (grid=128), 256 threads (8 warps = exactly 2/SMSP):
//      tid   0..127 : odd states  s=2*tid+1  (11 MUFU / 2 steps) [producers]
//      tid 128..255 : even states s=2*(tid-128) (7 MUFU / 2 steps)
//      thread 127   : additionally state 256 (+4 MUFU, reuses own b0)
//    Parity-pure warps -> no divergence; blank (even) updates are 2-term.
//  - Per 2-step iteration each thread reads alpha_t[s-4..s] from the shared
//    double buffer (4-entry NEGV front pad -> branch-free), computes the
//    needed step-t ghost values + its own step-(t+1) value, stores alpha_{t+2}.
//    ONE __syncthreads per 2 steps.
//  - Probability rows staged into an 8-deep shared ring via coalesced
//    cp.async.cg (tid<128, 2 rows per commit group, wait_group<2> pre-barrier).
//  - log2-domain recursion (raw ex2/lg2.approx), final scaled by ln2.

#define NEGV (-1e30f)
#define EPSV (1e-7f)
#define LN2F (0.6931471805599453f)

constexpr int Bc = 128;
constexpr int Tc = 1024;
constexpr int Vc = 512;
constexpr int Lc = 128;
constexpr int Sc = 257;     // 2L+1
constexpr int D  = 8;       // ring stages (16KB)
constexpr int NT = 256;     // 8 warps

__device__ __forceinline__ float ex2f(float x) {
    float r; asm("ex2.approx.f32 %0, %1;" : "=f"(r) : "f"(x)); return r;
}
__device__ __forceinline__ float lg2f(float x) {
    float r; asm("lg2.approx.f32 %0, %1;" : "=f"(r) : "f"(x)); return r;
}
__device__ __forceinline__ void cp_async16(uint32_t saddr, const void* gptr) {
    asm volatile("cp.async.cg.shared.global [%0], [%1], 16;" :: "r"(saddr), "l"(gptr));
}
__device__ __forceinline__ void cp_commit() {
    asm volatile("cp.async.commit_group;");
}
template<int N>
__device__ __forceinline__ void cp_wait() {
    asm volatile("cp.async.wait_group %0;" :: "n"(N));
}

// 3-term: m + lg2((1 + 2^(lo-m) + 2^(x-m)) * p)   [3 MUFU]
__device__ __forceinline__ float up3(float a, float b, float c, float p) {
    const float hi = fmaxf(a, b);
    const float lo = fminf(a, b);
    const float m  = fmaxf(hi, c);
    const float x  = fminf(hi, c);
    return m + lg2f((1.0f + ex2f(lo - m) + ex2f(x - m)) * p);
}
// 2-term: m + lg2((1 + 2^(lo-m)) * p)             [2 MUFU]
__device__ __forceinline__ float up2(float a, float b, float p) {
    const float m  = fmaxf(a, b);
    const float lo = fminf(a, b);
    return m + lg2f((1.0f + ex2f(lo - m)) * p);
}

__global__ __launch_bounds__(NT, 1)
void ctc_forward_kernel(const int*   __restrict__ labels,     // [B, L]
                        const int*   __restrict__ lab_len,    // [B, 1]
                        const float* __restrict__ Y,          // [B, T, V]
                        const int*   __restrict__ in_len,     // [B, 1]
                        float*       __restrict__ out)        // [B, 1]
{
    __shared__ __align__(16) float rows[D][Vc];   // staged probability rows
    __shared__ float As[2][Sc + 8];               // alpha: 4 front-pad + 257 + tail
    __shared__ int   lab_sh[Lc];

    const int b   = blockIdx.x;
    const int tid = threadIdx.x;

    if (tid < Lc) lab_sh[tid] = labels[b * Lc + tid];
    const int len = in_len[b];

    const bool odd = (tid < 128);
    const int  s   = odd ? (2 * tid + 1) : (2 * (tid - 128));
    const bool xtra = (tid == 127);               // also owns state 256

    // init: front pads (both buffers) + alpha0 (log2 domain)
    if (tid < 4) { As[0][tid] = NEGV; As[1][tid] = NEGV; }
    As[0][4 + s] = (s == 0) ? 0.0f : NEGV;
    if (xtra) As[0][4 + 256] = NEGV;

    const float* __restrict__ Yb = Y + (size_t)b * Tc * Vc;
    const uint32_t rows_sb = (uint32_t)__cvta_generic_to_shared(&rows[0][0]);

    // ---- prologue: stage rows 0..D-1 (2 rows per commit group) ----
    if (odd) {
        #pragma unroll
        for (int g = 0; g < D / 2; g++) {
            #pragma unroll
            for (int r = 0; r < 2; r++) {
                const int j  = 2 * g + r;
                const int tr = (j < len) ? j : (len > 0 ? len - 1 : 0);
                cp_async16(rows_sb + (uint32_t)j * 2048u + (uint32_t)tid * 16u,
                           Yb + (size_t)tr * Vc + tid * 4);
            }
            cp_commit();
        }
        cp_wait<2>();                 // rows 0..3 complete
    }
    __syncthreads();                  // labels, alpha0, rows visible

    // ---- per-thread constants ----
    const int blank = Vc - 1;
    int  clsA = blank;                // own-state class (odd) / b1 class (even)
    bool csA  = false, csB = false;
    if (odd) {
        const int l = tid;            // s = 2l+1
        clsA = lab_sh[l];                                   // state s class
        const int lm1 = (l >= 1) ? (l - 1) : 0;
        csA = (l >= 1) && (clsA != lab_sh[lm1]) && (clsA != blank);
        // b2 = state s-2 = 2l-1 (label l-1):
        csB = (l >= 2) && (lab_sh[l - 1] != lab_sh[l - 2]) && (lab_sh[l - 1] != blank);
    } else {
        const int l = tid - 128;      // s = 2l
        const int lm1 = (l >= 1) ? (l - 1) : 0;
        clsA = lab_sh[lm1];                                 // b1 = state 2l-1 class
        csB = (l >= 2) && (lab_sh[l - 1] != lab_sh[l - 2]) && (lab_sh[l - 1] != blank);
    }
    int clsM2 = blank;                // odd-only: b2's class (label l-1)
    if (odd) clsM2 = lab_sh[(tid >= 1) ? (tid - 1) : 0];

    // ---- main recursion: 2 steps per barrier ----
    int rd = 0;
    for (int t = 0; t < len; t += 2) {
        const float* __restrict__ r0 = rows[t & (D - 1)];
        const float* __restrict__ r1 = rows[(t + 1) & (D - 1)];
        const float* __restrict__ A  = &As[rd][4];    // A[i] = alpha_t[i]
        const bool   two = (t + 1 < len);

        if (odd) {
            const float A0 = A[s];
            const float A1 = A[s - 1];
            const float A2 = A[s - 2];
            const float A3 = A[s - 3];
            const float A4 = A[s - 4];
            const float pS  = r0[clsA]  + EPSV;
            const float pB  = r0[blank] + EPSV;
            const float pM2 = r0[clsM2] + EPSV;
            const float qS  = r1[clsA]  + EPSV;

            const float b0 = up3(A0, A1, csA ? A2 : NEGV, pS);   // state s, step t
            const float b1 = up2(A1, A2, pB);                    // state s-1 (blank)
            const float b2 = up3(A2, A3, csB ? A4 : NEGV, pM2);  // state s-2
            const float n  = two ? up3(b0, b1, csA ? b2 : NEGV, qS) : b0;
            As[rd ^ 1][4 + s] = n;

            if (xtra) {                                          // state 256 (blank)
                const float qB  = r1[blank] + EPSV;
                const float b0x = up2(A[256], A[255], pB);       // step t
                const float nx  = two ? up2(b0x, b0, qB) : b0x;  // b0 = state255_t
                As[rd ^ 1][4 + 256] = nx;
            }
        } else {
            const float A0 = A[s];
            const float A1 = A[s - 1];
            const float A2 = A[s - 2];
            const float A3 = A[s - 3];
            const float pB  = r0[blank] + EPSV;
            const float pM1 = r0[clsA]  + EPSV;
            const float qB  = r1[blank] + EPSV;

            const float b0 = up2(A0, A1, pB);                    // state s (blank)
            const float b1 = up3(A1, A2, csB ? A3 : NEGV, pM1);  // state s-1
            const float n  = two ? up2(b0, b1, qB) : b0;
            As[rd ^ 1][4 + s] = n;
        }

        if (odd) cp_wait<2>();        // next iteration's rows complete
        __syncthreads();              // publish alpha_{t+2} and staged rows
        if (odd && (t + D) < len) {
            #pragma unroll
            for (int r = 0; r < 2; r++) {
                const int j  = t + D + r;
                const int tr = (j < len) ? j : (len - 1);
                cp_async16(rows_sb + (uint32_t)(j & (D - 1)) * 2048u + (uint32_t)tid * 16u,
                           Yb + (size_t)tr * Vc + tid * 4);
            }
            cp_commit();
        }
        rd ^= 1;
    }

    // ---- final: loss = -ln2 * logaddexp2(alpha[2*lab], alpha[2*lab-1]) ----
    if (tid == 0) {
        const int   ll = lab_len[b];
        const float aL = As[rd][4 + 2 * ll];
        const float aP = As[rd][4 + 2 * ll - 1];
        const float mm = fmaxf(aL, aP);
        const float ql = fminf(aL, aP);
        out[b] = -LN2F * (mm + lg2f(1.0f + ex2f(ql - mm)));
    }
}

extern "C" void kernel_launch(void* const* d_in, const int* in_sizes, int n_in,
                              void* d_out, int out_size) {
    const int*   labels  = (const int*)d_in[0];   // true_labels [B, L]
    const int*   lab_len = (const int*)d_in[1];   // true_lengths [B, 1]
    const float* Y       = (const float*)d_in[2]; // predicted_labels [B, T, V]
    const int*   in_len  = (const int*)d_in[3];   // predicted_lengths [B, 1]
    float*       out     = (float*)d_out;         // [B, 1]

    ctc_forward_kernel<<<Bc, NT>>>(labels, lab_len, Y, in_len, out);
}

// round 11
// speedup vs baseline: 1.5336x; 1.5336x over previous
#include <cuda_runtime.h>
#include <cuda_bf16.h>
#include <cstdint>

// CTC forward negative log-likelihood (keras ctc_batch_cost semantics).
// B=128, T=1024, V=512, L=128, S=2L+1=257, blank=V-1.
//
// Round-11 design ("composed 2-step update, linear path weights"):
//  - R9 scaffold: 1 CTA/batch (grid=128), 288 threads, thread s=tid owns state
//    s (conflict-free alpha LDS/STS), 4-entry NEGV front pad, ONE
//    __syncthreads per 2 time steps, cp.async 8-deep row ring (tid<128).
//  - NEW: the two steps are composed algebraically:
//      alpha_{t+2}[s] = m + lg2( (sum_j W_j * 2^(alpha_t[s-j]-m)) * q_s )
//    with LINEAR path weights (pure FMA, off the MUFU chain):
//      W0 = p_s
//      W1 = p_s + p_m1
//      W2 = cs_s ? (p_s + p_m1 + p_m2) : p_m1
//      W3 = (cs_m1 ? p_m1 : 0) + (cs_s ? p_m2 : 0)
//      W4 = (cs_s && cs_m2) ? p_m2 : 0
//    (p_x = row_t[class(x)] + EPS, q_s = row_{t+1}[class(s)] + EPS).
//    Exactly equivalent to two chained logaddexp2 steps (same EPS placement).
//  - alpha terms with possibly-zero weight (j=3,4) are masked to NEG in the
//    max via precomputed predicates -> factored max always has W>0.
//  - Gathered p/q values are prefetched ONE iteration ahead (rows t+2/t+3 are
//    complete at iteration-t start), so no scattered LDS on the serial path.
//  - Critical-chain MUFU: 5 parallel ex2 + 1 lg2 (was 2 chained 3-MUFU up3s).

#define NEGV (-1e30f)
#define EPSV (1e-7f)
#define LN2F (0.6931471805599453f)

constexpr int Bc = 128;
constexpr int Tc = 1024;
constexpr int Vc = 512;
constexpr int Lc = 128;
constexpr int Sc = 257;     // 2L+1
constexpr int D  = 8;       // ring stages (16KB)
constexpr int NT = 288;     // 9 warps

__device__ __forceinline__ float ex2f(float x) {
    float r; asm("ex2.approx.f32 %0, %1;" : "=f"(r) : "f"(x)); return r;
}
__device__ __forceinline__ float lg2f(float x) {
    float r; asm("lg2.approx.f32 %0, %1;" : "=f"(r) : "f"(x)); return r;
}
__device__ __forceinline__ void cp_async16(uint32_t saddr, const void* gptr) {
    asm volatile("cp.async.cg.shared.global [%0], [%1], 16;" :: "r"(saddr), "l"(gptr));
}
__device__ __forceinline__ void cp_commit() {
    asm volatile("cp.async.commit_group;");
}
template<int N>
__device__ __forceinline__ void cp_wait() {
    asm volatile("cp.async.wait_group %0;" :: "n"(N));
}

__global__ __launch_bounds__(NT, 1)
void ctc_forward_kernel(const int*   __restrict__ labels,     // [B, L]
                        const int*   __restrict__ lab_len,    // [B, 1]
                        const float* __restrict__ Y,          // [B, T, V]
                        const int*   __restrict__ in_len,     // [B, 1]
                        float*       __restrict__ out)        // [B, 1]
{
    __shared__ __align__(16) float rows[D][Vc];   // staged probability rows
    __shared__ float As[2][Sc + 8];               // alpha: 4 front-pad + 257 + tail
    __shared__ int   lab_sh[Lc];

    const int b   = blockIdx.x;
    const int tid = threadIdx.x;

    if (tid < Lc) lab_sh[tid] = labels[b * Lc + tid];
    const int len = in_len[b];

    const bool active = (tid <= 256);
    const int  s      = tid;

    if (tid < 4) { As[0][tid] = NEGV; As[1][tid] = NEGV; }
    if (active) As[0][4 + s] = (s == 0) ? 0.0f : NEGV;    // log2 domain

    const float* __restrict__ Yb = Y + (size_t)b * Tc * Vc;
    const bool producer = (tid < 128);
    const uint32_t rows_sb = (uint32_t)__cvta_generic_to_shared(&rows[0][0]);

    // ---- prologue: stage rows 0..D-1 (2 rows per commit group) ----
    if (producer) {
        #pragma unroll
        for (int g = 0; g < D / 2; g++) {
            #pragma unroll
            for (int r = 0; r < 2; r++) {
                const int j  = 2 * g + r;
                const int tr = (j < len) ? j : (len > 0 ? len - 1 : 0);
                cp_async16(rows_sb + (uint32_t)j * 2048u + (uint32_t)tid * 16u,
                           Yb + (size_t)tr * Vc + tid * 4);
            }
            cp_commit();
        }
        cp_wait<2>();                 // rows 0..3 complete
    }
    __syncthreads();                  // labels, alpha0, rows 0..3 visible

    // ---- per-thread constants (classes + skip flags for s, s-1, s-2) ----
    const int  blank = Vc - 1;
    const bool sOdd  = (s & 1) != 0;
    int  cls_s  = blank, cls_m1 = blank, cls_m2 = blank;
    bool cs_s = false, cs_m1 = false, cs_m2 = false;
    if (active) {
        if (sOdd) {
            cls_s  = lab_sh[(s - 1) >> 1];
            cls_m2 = (s >= 3) ? lab_sh[(s - 3) >> 1] : blank;
            cs_s   = (s >= 3) && (cls_s != cls_m2) && (cls_s != blank);
            cs_m2  = (s >= 5) && (lab_sh[(s - 3) >> 1] != lab_sh[(s - 5) >> 1])
                              && (cls_m2 != blank);
        } else {
            cls_m1 = (s >= 2) ? lab_sh[(s - 2) >> 1] : blank;
            cs_m1  = (s >= 4) && (lab_sh[(s - 2) >> 1] != lab_sh[(s - 4) >> 1])
                              && (cls_m1 != blank);
        }
    }
    const bool pm3 = cs_m1 || cs_s;       // W3 > 0 ?
    const bool pm4 = cs_s && cs_m2;       // W4 > 0 ?

    // ---- prefetch p/q for iteration t=0 ----
    float P0 = EPSV, P1 = EPSV, P2 = EPSV, Qs = EPSV;
    if (active) {
        P0 = rows[0][cls_s]  + EPSV;
        P1 = rows[0][cls_m1] + EPSV;
        P2 = rows[0][cls_m2] + EPSV;
        Qs = rows[1][cls_s]  + EPSV;
    }

    // ---- main recursion: 2 composed steps per barrier ----
    int rd = 0;
    int t  = 0;
    for (; t + 1 < len; t += 2) {
        if (active) {
            // linear path weights (FMA/ALU only)
            const float W0 = P0;
            const float W1 = P0 + P1;
            const float W2 = cs_s ? (W1 + P2) : P1;
            const float W3 = (cs_m1 ? P1 : 0.0f) + (cs_s ? P2 : 0.0f);
            const float W4 = pm4 ? P2 : 0.0f;

            const float* __restrict__ A = &As[rd][4];   // A[i] = alpha_t[i]
            const float A0 = A[s];
            const float A1 = A[s - 1];
            const float A2 = A[s - 2];
            const float A3 = pm3 ? A[s - 3] : NEGV;     // mask zero-weight terms
            const float A4 = pm4 ? A[s - 4] : NEGV;

            const float m = fmaxf(fmaxf(fmaxf(A0, A1), fmaxf(A2, A3)), A4);
            const float x0 = ex2f(A0 - m);
            const float x1 = ex2f(A1 - m);
            const float x2 = ex2f(A2 - m);
            const float x3 = ex2f(A3 - m);
            const float x4 = ex2f(A4 - m);
            const float sum = (W0 * x0 + W1 * x1) + (W2 * x2 + (W3 * x3 + W4 * x4));
            As[rd ^ 1][4 + s] = m + lg2f(sum * Qs);

            // prefetch p/q for iteration t+2 (rows t+2, t+3 complete)
            const float* __restrict__ r0n = rows[(t + 2) & (D - 1)];
            const float* __restrict__ r1n = rows[(t + 3) & (D - 1)];
            P0 = r0n[cls_s]  + EPSV;
            P1 = r0n[cls_m1] + EPSV;
            P2 = r0n[cls_m2] + EPSV;
            Qs = r1n[cls_s]  + EPSV;
        }

        if (producer) cp_wait<2>();   // rows t+4, t+5 complete
        __syncthreads();              // publish alpha_{t+2}, retire slots
        if (producer && (t + D) < len) {
            #pragma unroll
            for (int r = 0; r < 2; r++) {
                const int j  = t + D + r;
                const int tr = (j < len) ? j : (len - 1);
                cp_async16(rows_sb + (uint32_t)(j & (D - 1)) * 2048u + (uint32_t)tid * 16u,
                           Yb + (size_t)tr * Vc + tid * 4);
            }
            cp_commit();
        }
        rd ^= 1;
    }

    // ---- odd tail: one single step (len odd) ----
    if (t < len) {
        if (active) {
            const float* __restrict__ A = &As[rd][4];
            const float A0 = A[s];
            const float A1 = A[s - 1];
            const float A2 = cs_s ? A[s - 2] : NEGV;
            const float m  = fmaxf(fmaxf(A0, A1), A2);
            const float sum = ex2f(A0 - m) + ex2f(A1 - m) + ex2f(A2 - m);
            As[rd ^ 1][4 + s] = m + lg2f(sum * P0);   // P0 = p_s at row t
        }
        __syncthreads();
        rd ^= 1;
    }

    // ---- final: loss = -ln2 * logaddexp2(alpha[2*lab], alpha[2*lab-1]) ----
    if (tid == 0) {
        const int   ll = lab_len[b];
        const float aL = As[rd][4 + 2 * ll];
        const float aP = As[rd][4 + 2 * ll - 1];
        const float mm = fmaxf(aL, aP);
        const float ql = fminf(aL, aP);
        out[b] = -LN2F * (mm + lg2f(1.0f + ex2f(ql - mm)));
    }
}

extern "C" void kernel_launch(void* const* d_in, const int* in_sizes, int n_in,
                              void* d_out, int out_size) {
    const int*   labels  = (const int*)d_in[0];   // true_labels [B, L]
    const int*   lab_len = (const int*)d_in[1];   // true_lengths [B, 1]
    const float* Y       = (const float*)d_in[2]; // predicted_labels [B, T, V]
    const int*   in_len  = (const int*)d_in[3];   // predicted_lengths [B, 1]
    float*       out     = (float*)d_out;         // [B, 1]

    ctc_forward_kernel<<<Bc, NT>>>(labels, lab_len, Y, in_len, out);
}